// round 1
// baseline (speedup 1.0000x reference)
#include <cuda_runtime.h>
#include <math_constants.h>

// Problem shape (fixed by the dataset): B=32, H=16, N=1024, D=128, fp32.
#define Bc 32
#define Hc 16
#define Nc 1024
#define Dc 128
#define NWARPS 16           // 512 threads / block in kernel 1
#define D4 (Dc / 4)         // 32 float4 per row

// Scratch: per-(b,h,n) multiplicative factor = attn + 1 (masked rows -> 1.0).
// 32*16*1024 floats = 2 MB. Device global (no allocation allowed).
__device__ float g_factor[Bc * Hc * Nc];

// ---------------------------------------------------------------------------
// Kernel 1: one block per (b, h).
//   - streams transformer_t_1[b,h]  -> accumulates  sum_n dot(row, w1)
//   - streams transformer_t  [b,h]  -> score[n] = dot(row, w2)   (into smem)
//   - computes padd[b] from padding_t
//   - softmax over valid n, writes factor = attn + 1 to g_factor
// ---------------------------------------------------------------------------
__global__ __launch_bounds__(512, 3)
void score_softmax_kernel(const float* __restrict__ t1,
                          const float* __restrict__ t,
                          const int*   __restrict__ padding,
                          const float* __restrict__ w,     // [256]: w1 | w2
                          const float* __restrict__ bias)  // [1]
{
    __shared__ float s_score[Nc];      // 4 KB
    __shared__ float s_sum1[NWARPS];
    __shared__ float s_max[NWARPS];
    __shared__ float s_esum[NWARPS];
    __shared__ int   s_padd;

    const int bh   = blockIdx.x;
    const int b    = bh / Hc;
    const int tid  = threadIdx.x;
    const int wid  = tid >> 5;
    const int lane = tid & 31;

    const float4* t1b = reinterpret_cast<const float4*>(t1) + (size_t)bh * Nc * D4;
    const float4* tb  = reinterpret_cast<const float4*>(t)  + (size_t)bh * Nc * D4;

    // Each lane owns dims [4*lane, 4*lane+4) of D=128.
    const float4 w1v = reinterpret_cast<const float4*>(w)[lane];
    const float4 w2v = reinterpret_cast<const float4*>(w)[D4 + lane];

    if (tid == 0) s_padd = Nc;
    __syncthreads();

    // ---- padd[b] = first index where padding_t == 0 (else N) ----
    {
        const int* pb = padding + b * Nc;
        int local = Nc;
        #pragma unroll
        for (int n = tid; n < Nc; n += 512)
            if (pb[n] == 0) local = min(local, n);
        if (local < Nc) atomicMin(&s_padd, local);
    }

    // ---- stream rows: t1 dot w1 (accumulate), t dot w2 (per-row score) ----
    float sum1 = 0.f;
    for (int n = wid; n < Nc; n += NWARPS) {
        float4 a = t1b[n * D4 + lane];
        sum1 += a.x * w1v.x + a.y * w1v.y + a.z * w1v.z + a.w * w1v.w;

        float4 c = tb[n * D4 + lane];
        float sc = c.x * w2v.x + c.y * w2v.y + c.z * w2v.z + c.w * w2v.w;
        #pragma unroll
        for (int o = 16; o > 0; o >>= 1)
            sc += __shfl_xor_sync(0xffffffffu, sc, o);
        if (lane == 0) s_score[n] = sc;
    }
    #pragma unroll
    for (int o = 16; o > 0; o >>= 1)
        sum1 += __shfl_xor_sync(0xffffffffu, sum1, o);
    if (lane == 0) s_sum1[wid] = sum1;
    __syncthreads();   // s_score, s_sum1, s_padd all complete

    float base = bias[0];
    #pragma unroll
    for (int i = 0; i < NWARPS; i++) base += s_sum1[i];
    const int padd = s_padd;

    // ---- softmax over valid n (each thread owns n = tid, tid+512) ----
    float m = -CUDART_INF_F;
    #pragma unroll
    for (int n = tid; n < Nc; n += 512) {
        float sc = s_score[n] + base;
        s_score[n] = sc;
        if (n < padd) m = fmaxf(m, sc);
    }
    #pragma unroll
    for (int o = 16; o > 0; o >>= 1)
        m = fmaxf(m, __shfl_xor_sync(0xffffffffu, m, o));
    if (lane == 0) s_max[wid] = m;
    __syncthreads();
    float mx = -CUDART_INF_F;
    #pragma unroll
    for (int i = 0; i < NWARPS; i++) mx = fmaxf(mx, s_max[i]);

    float esum = 0.f;
    #pragma unroll
    for (int n = tid; n < Nc; n += 512) {
        float e = (n < padd) ? __expf(s_score[n] - mx) : 0.f;
        s_score[n] = e;
        esum += e;
    }
    #pragma unroll
    for (int o = 16; o > 0; o >>= 1)
        esum += __shfl_xor_sync(0xffffffffu, esum, o);
    if (lane == 0) s_esum[wid] = esum;
    __syncthreads();
    float tot = 0.f;
    #pragma unroll
    for (int i = 0; i < NWARPS; i++) tot += s_esum[i];
    const float inv = 1.f / tot;

    float* fout = g_factor + bh * Nc;
    #pragma unroll
    for (int n = tid; n < Nc; n += 512)
        fout[n] = fmaf(s_score[n], inv, 1.f);   // masked e==0 -> factor 1
}

// ---------------------------------------------------------------------------
// Kernel 2: out[b,h,n,:] = t[b,h,n,:] * factor[b,h,n]   (pure stream, float4)
// ---------------------------------------------------------------------------
__global__ __launch_bounds__(256)
void scale_kernel(const float* __restrict__ t, float* __restrict__ out)
{
    const size_t total4 = (size_t)Bc * Hc * Nc * D4;     // 16,777,216
    size_t i = (size_t)blockIdx.x * blockDim.x + threadIdx.x;
    const size_t stride = (size_t)gridDim.x * blockDim.x;
    const float4* tv = reinterpret_cast<const float4*>(t);
    float4* ov = reinterpret_cast<float4*>(out);
    for (; i < total4; i += stride) {
        float f = g_factor[i >> 5];          // 32 float4 per (b,h,n) row
        float4 v = tv[i];
        v.x *= f; v.y *= f; v.z *= f; v.w *= f;
        ov[i] = v;
    }
}

extern "C" void kernel_launch(void* const* d_in, const int* in_sizes, int n_in,
                              void* d_out, int out_size)
{
    const float* t1      = (const float*)d_in[0];
    const float* t       = (const float*)d_in[1];
    const int*   padding = (const int*)d_in[2];

    // concat_w is the input with 256 elements among the tail inputs
    // (max_n_codes may or may not be materialized as a size-1 input);
    // concat_b is always the last input.
    const float* w = nullptr;
    for (int i = 3; i < n_in; i++)
        if (in_sizes[i] == 2 * Dc) { w = (const float*)d_in[i]; }
    const float* bias = (const float*)d_in[n_in - 1];

    float* out = (float*)d_out;

    score_softmax_kernel<<<Bc * Hc, 512>>>(t1, t, padding, w, bias);

    const size_t total4 = (size_t)Bc * Hc * Nc * D4;
    int threads = 256;
    int blocks  = 148 * 16;                  // grid-stride, ~44 f4/thread
    (void)total4; (void)out_size;
    scale_kernel<<<blocks, threads>>>(t, out);
}

// round 2
// speedup vs baseline: 1.0905x; 1.0905x over previous
#include <cuda_runtime.h>
#include <math_constants.h>

// Problem shape (fixed by the dataset): B=32, H=16, N=1024, D=128, fp32.
#define Bc 32
#define Hc 16
#define Nc 1024
#define Dc 128
#define NWARPS 16           // 512 threads / block in kernel 1
#define D4 (Dc / 4)         // 32 float4 per row

// Scratch: per-(b,h,n) multiplicative factor = attn + 1 (masked rows -> 1.0).
__device__ float g_factor[Bc * Hc * Nc];

// ---------------------------------------------------------------------------
// Kernel 1: one block per (b, h).
// Warp layout: 4 rows per warp-iteration, 8 lanes per row.
//   lane = (g = lane>>3 : row-in-quad, sub = lane&7 : dim-chunk)
//   lane reads float4 indices {sub, sub+8, sub+16, sub+24} of its row.
// Row-score reduce = 3-shfl butterfly over the 8-lane group (4 rows at once).
// ---------------------------------------------------------------------------
__global__ __launch_bounds__(512, 2)
void score_softmax_kernel(const float* __restrict__ t1,
                          const float* __restrict__ t,
                          const int*   __restrict__ padding,
                          const float* __restrict__ w,     // [256]: w1 | w2
                          const float* __restrict__ bias)  // [1]
{
    __shared__ float s_score[Nc];      // 4 KB
    __shared__ float s_sum1[NWARPS];
    __shared__ float s_max[NWARPS];
    __shared__ float s_esum[NWARPS];
    __shared__ int   s_padd;

    const int bh   = blockIdx.x;
    const int b    = bh / Hc;
    const int tid  = threadIdx.x;
    const int wid  = tid >> 5;
    const int lane = tid & 31;
    const int g    = lane >> 3;    // row within quad
    const int sub  = lane & 7;     // dim-chunk id

    const float4* t1b = reinterpret_cast<const float4*>(t1) + (size_t)bh * Nc * D4;
    const float4* tb  = reinterpret_cast<const float4*>(t)  + (size_t)bh * Nc * D4;

    // Per-lane weight segments: float4 indices sub + k*8, k = 0..3.
    const float4* wf = reinterpret_cast<const float4*>(w);
    float4 w1v[4], w2v[4];
    #pragma unroll
    for (int k = 0; k < 4; k++) {
        w1v[k] = wf[sub + k * 8];
        w2v[k] = wf[D4 + sub + k * 8];
    }

    if (tid == 0) s_padd = Nc;
    __syncthreads();

    // ---- padd[b] = first index where padding_t == 0 (else N) ----
    {
        const int* pb = padding + b * Nc;
        int local = Nc;
        #pragma unroll
        for (int n = tid; n < Nc; n += 512)
            if (pb[n] == 0) local = min(local, n);
        if (local < Nc) atomicMin(&s_padd, local);
    }

    // ---- stream rows: t1 dot w1 (accumulate), t dot w2 (per-row score) ----
    float sum1 = 0.f;
    #pragma unroll 4
    for (int r0 = wid * 4; r0 < Nc; r0 += NWARPS * 4) {   // 16 iters/warp
        const int row = r0 + g;
        const float4* trow  = tb  + row * D4;
        const float4* t1row = t1b + row * D4;

        float sc = 0.f, s1 = 0.f;
        #pragma unroll
        for (int k = 0; k < 4; k++) {
            float4 c = trow[sub + k * 8];
            sc += c.x * w2v[k].x + c.y * w2v[k].y + c.z * w2v[k].z + c.w * w2v[k].w;
            float4 a = t1row[sub + k * 8];
            s1 += a.x * w1v[k].x + a.y * w1v[k].y + a.z * w1v[k].z + a.w * w1v[k].w;
        }
        sum1 += s1;

        // 8-lane butterfly: all 4 rows reduced with 3 shuffles total
        sc += __shfl_xor_sync(0xffffffffu, sc, 1);
        sc += __shfl_xor_sync(0xffffffffu, sc, 2);
        sc += __shfl_xor_sync(0xffffffffu, sc, 4);
        if (sub == 0) s_score[row] = sc;
    }
    // sum1: full 32-lane reduce (all lanes hold disjoint partials)
    #pragma unroll
    for (int o = 16; o > 0; o >>= 1)
        sum1 += __shfl_xor_sync(0xffffffffu, sum1, o);
    if (lane == 0) s_sum1[wid] = sum1;
    __syncthreads();   // s_score, s_sum1, s_padd all complete

    float base = bias[0];
    #pragma unroll
    for (int i = 0; i < NWARPS; i++) base += s_sum1[i];
    const int padd = s_padd;

    // ---- softmax over valid n (each thread owns n = tid, tid+512) ----
    float m = -CUDART_INF_F;
    #pragma unroll
    for (int n = tid; n < Nc; n += 512) {
        float sc = s_score[n] + base;
        s_score[n] = sc;
        if (n < padd) m = fmaxf(m, sc);
    }
    #pragma unroll
    for (int o = 16; o > 0; o >>= 1)
        m = fmaxf(m, __shfl_xor_sync(0xffffffffu, m, o));
    if (lane == 0) s_max[wid] = m;
    __syncthreads();
    float mx = -CUDART_INF_F;
    #pragma unroll
    for (int i = 0; i < NWARPS; i++) mx = fmaxf(mx, s_max[i]);

    float esum = 0.f;
    #pragma unroll
    for (int n = tid; n < Nc; n += 512) {
        float e = (n < padd) ? __expf(s_score[n] - mx) : 0.f;
        s_score[n] = e;
        esum += e;
    }
    #pragma unroll
    for (int o = 16; o > 0; o >>= 1)
        esum += __shfl_xor_sync(0xffffffffu, esum, o);
    if (lane == 0) s_esum[wid] = esum;
    __syncthreads();
    float tot = 0.f;
    #pragma unroll
    for (int i = 0; i < NWARPS; i++) tot += s_esum[i];
    const float inv = (tot > 0.f) ? (1.f / tot) : 0.f;   // all-masked guard

    float* fout = g_factor + bh * Nc;
    #pragma unroll
    for (int n = tid; n < Nc; n += 512)
        fout[n] = fmaf(s_score[n], inv, 1.f);   // masked e==0 -> factor 1
}

// ---------------------------------------------------------------------------
// Kernel 2: out[b,h,n,:] = t[b,h,n,:] * factor[b,h,n]   (pure stream, float4)
// ---------------------------------------------------------------------------
__global__ __launch_bounds__(256)
void scale_kernel(const float* __restrict__ t, float* __restrict__ out)
{
    const size_t total4 = (size_t)Bc * Hc * Nc * D4;     // 16,777,216
    size_t i = (size_t)blockIdx.x * blockDim.x + threadIdx.x;
    const size_t stride = (size_t)gridDim.x * blockDim.x;
    const float4* tv = reinterpret_cast<const float4*>(t);
    float4* ov = reinterpret_cast<float4*>(out);
    for (; i < total4; i += stride) {
        float f = g_factor[i >> 5];          // 32 float4 per (b,h,n) row
        float4 v = tv[i];
        v.x *= f; v.y *= f; v.z *= f; v.w *= f;
        ov[i] = v;
    }
}

extern "C" void kernel_launch(void* const* d_in, const int* in_sizes, int n_in,
                              void* d_out, int out_size)
{
    const float* t1      = (const float*)d_in[0];
    const float* t       = (const float*)d_in[1];
    const int*   padding = (const int*)d_in[2];

    const float* w = nullptr;
    for (int i = 3; i < n_in; i++)
        if (in_sizes[i] == 2 * Dc) { w = (const float*)d_in[i]; }
    const float* bias = (const float*)d_in[n_in - 1];

    float* out = (float*)d_out;

    score_softmax_kernel<<<Bc * Hc, 512>>>(t1, t, padding, w, bias);

    scale_kernel<<<148 * 16, 256>>>(t, out);
    (void)out_size;
}

// round 3
// speedup vs baseline: 1.1605x; 1.0642x over previous
#include <cuda_runtime.h>
#include <math_constants.h>

// Problem shape (fixed by the dataset): B=32, H=16, N=1024, D=128, fp32.
#define Bc 32
#define Hc 16
#define Nc 1024
#define Dc 128
#define D4 (Dc / 4)                 // 32 float4 per row
#define NROWS (Bc * Hc * Nc)        // 524288 rows total
#define NQUADS (NROWS / 4)          // 131072? no: rows/4 = 131072... see below

// NOTE: rows = 32*16*1024 = 524288?  B*H*N = 32*16*1024 = 524288. Quads = 131072.
// Each warp does one quad => 131072 warps => 16384 blocks of 256 threads.

// Scratch (device globals; allocation is forbidden).
__device__ float g_score [NROWS];        // per-row score (t . w2)      2 MB
__device__ float g_part  [NROWS / 4];    // per-quad partial of t1 . w1 512 KB
__device__ float g_factor[NROWS];        // attn + 1                    2 MB

// ---------------------------------------------------------------------------
// Kernel A: one quad (4 consecutive rows, all within one bh) per warp.
// Lane split: g = lane>>3 (row in quad), sub = lane&7 (dim chunk).
// Lane reads float4 indices {sub, sub+8, sub+16, sub+24} of its row.
// ---------------------------------------------------------------------------
__global__ __launch_bounds__(256)
void score_kernel(const float* __restrict__ t1,
                  const float* __restrict__ t,
                  const float* __restrict__ w)      // [256]: w1 | w2
{
    const int warp  = (blockIdx.x * blockDim.x + threadIdx.x) >> 5;
    const int lane  = threadIdx.x & 31;
    const int g     = lane >> 3;
    const int sub   = lane & 7;

    const int quad = warp;                  // one quad per warp
    const int row  = quad * 4 + g;

    const float4* trow  = reinterpret_cast<const float4*>(t)  + (size_t)row * D4;
    const float4* t1row = reinterpret_cast<const float4*>(t1) + (size_t)row * D4;
    const float4* wf    = reinterpret_cast<const float4*>(w);

    // Issue all 16 data loads + 8 weight loads; weights are L1-broadcast.
    float4 c0 = __ldcs(trow  + sub);
    float4 c1 = __ldcs(trow  + sub + 8);
    float4 c2 = __ldcs(trow  + sub + 16);
    float4 c3 = __ldcs(trow  + sub + 24);
    float4 a0 = __ldcs(t1row + sub);
    float4 a1 = __ldcs(t1row + sub + 8);
    float4 a2 = __ldcs(t1row + sub + 16);
    float4 a3 = __ldcs(t1row + sub + 24);

    float4 u0 = wf[D4 + sub],      u1 = wf[D4 + sub + 8];
    float4 u2 = wf[D4 + sub + 16], u3 = wf[D4 + sub + 24];
    float4 v0 = wf[sub],           v1 = wf[sub + 8];
    float4 v2 = wf[sub + 16],      v3 = wf[sub + 24];

    float sc = c0.x*u0.x + c0.y*u0.y + c0.z*u0.z + c0.w*u0.w
             + c1.x*u1.x + c1.y*u1.y + c1.z*u1.z + c1.w*u1.w
             + c2.x*u2.x + c2.y*u2.y + c2.z*u2.z + c2.w*u2.w
             + c3.x*u3.x + c3.y*u3.y + c3.z*u3.z + c3.w*u3.w;

    float s1 = a0.x*v0.x + a0.y*v0.y + a0.z*v0.z + a0.w*v0.w
             + a1.x*v1.x + a1.y*v1.y + a1.z*v1.z + a1.w*v1.w
             + a2.x*v2.x + a2.y*v2.y + a2.z*v2.z + a2.w*v2.w
             + a3.x*v3.x + a3.y*v3.y + a3.z*v3.z + a3.w*v3.w;

    // 8-lane butterfly: reduces sc to per-row total, s1 partially.
    sc += __shfl_xor_sync(0xffffffffu, sc, 1);
    s1 += __shfl_xor_sync(0xffffffffu, s1, 1);
    sc += __shfl_xor_sync(0xffffffffu, sc, 2);
    s1 += __shfl_xor_sync(0xffffffffu, s1, 2);
    sc += __shfl_xor_sync(0xffffffffu, sc, 4);
    s1 += __shfl_xor_sync(0xffffffffu, s1, 4);
    // finish s1 across the 4 row-groups (full quad sum of t1 . w1)
    s1 += __shfl_xor_sync(0xffffffffu, s1, 8);
    s1 += __shfl_xor_sync(0xffffffffu, s1, 16);

    if (sub == 0) g_score[row] = sc;       // lanes 0,8,16,24
    if (lane == 0) g_part[quad] = s1;
}

// ---------------------------------------------------------------------------
// Kernel B: one block per (b,h). Reduce quad partials -> base, compute padd,
// softmax over scores, write factor = attn + 1.
// ---------------------------------------------------------------------------
__global__ __launch_bounds__(256)
void softmax_kernel(const int*   __restrict__ padding,
                    const float* __restrict__ bias)
{
    __shared__ float s_score[Nc];          // 4 KB
    __shared__ float s_red[8];
    __shared__ int   s_padd;

    const int bh   = blockIdx.x;
    const int b    = bh >> 4;              // Hc = 16
    const int tid  = threadIdx.x;
    const int wid  = tid >> 5;
    const int lane = tid & 31;

    if (tid == 0) s_padd = Nc;
    __syncthreads();

    // padd
    {
        const int* pb = padding + b * Nc;
        int local = Nc;
        #pragma unroll
        for (int n = tid; n < Nc; n += 256)
            if (pb[n] == 0) local = min(local, n);
        if (local < Nc) atomicMin(&s_padd, local);
    }

    // base = sum of 256 quad partials + bias
    float v = g_part[bh * (Nc / 4) + tid];
    #pragma unroll
    for (int o = 16; o > 0; o >>= 1) v += __shfl_xor_sync(0xffffffffu, v, o);
    if (lane == 0) s_red[wid] = v;
    __syncthreads();
    float base = bias[0];
    #pragma unroll
    for (int i = 0; i < 8; i++) base += s_red[i];
    const int padd = s_padd;

    // load scores + max over valid
    const float* sc_g = g_score + bh * Nc;
    float m = -CUDART_INF_F;
    #pragma unroll
    for (int n = tid; n < Nc; n += 256) {
        float sc = sc_g[n] + base;
        s_score[n] = sc;
        if (n < padd) m = fmaxf(m, sc);
    }
    #pragma unroll
    for (int o = 16; o > 0; o >>= 1)
        m = fmaxf(m, __shfl_xor_sync(0xffffffffu, m, o));
    __syncthreads();                        // reuse s_red
    if (lane == 0) s_red[wid] = m;
    __syncthreads();
    float mx = -CUDART_INF_F;
    #pragma unroll
    for (int i = 0; i < 8; i++) mx = fmaxf(mx, s_red[i]);

    float esum = 0.f;
    #pragma unroll
    for (int n = tid; n < Nc; n += 256) {
        float e = (n < padd) ? __expf(s_score[n] - mx) : 0.f;
        s_score[n] = e;
        esum += e;
    }
    #pragma unroll
    for (int o = 16; o > 0; o >>= 1)
        esum += __shfl_xor_sync(0xffffffffu, esum, o);
    __syncthreads();
    if (lane == 0) s_red[wid] = esum;
    __syncthreads();
    float tot = 0.f;
    #pragma unroll
    for (int i = 0; i < 8; i++) tot += s_red[i];
    const float inv = (tot > 0.f) ? (1.f / tot) : 0.f;

    float* fout = g_factor + bh * Nc;
    #pragma unroll
    for (int n = tid; n < Nc; n += 256)
        fout[n] = fmaf(s_score[n], inv, 1.f);
}

// ---------------------------------------------------------------------------
// Kernel C: out = t * factor[row]   (pure stream, float4)
// ---------------------------------------------------------------------------
__global__ __launch_bounds__(256)
void scale_kernel(const float* __restrict__ t, float* __restrict__ out)
{
    const size_t total4 = (size_t)NROWS * D4;
    size_t i = (size_t)blockIdx.x * blockDim.x + threadIdx.x;
    const size_t stride = (size_t)gridDim.x * blockDim.x;
    const float4* tv = reinterpret_cast<const float4*>(t);
    float4* ov = reinterpret_cast<float4*>(out);
    for (; i < total4; i += stride) {
        float f = g_factor[i >> 5];
        float4 val = __ldcs(tv + i);
        val.x *= f; val.y *= f; val.z *= f; val.w *= f;
        __stcs(ov + i, val);
    }
}

extern "C" void kernel_launch(void* const* d_in, const int* in_sizes, int n_in,
                              void* d_out, int out_size)
{
    const float* t1      = (const float*)d_in[0];
    const float* t       = (const float*)d_in[1];
    const int*   padding = (const int*)d_in[2];

    const float* w = nullptr;
    for (int i = 3; i < n_in; i++)
        if (in_sizes[i] == 2 * Dc) { w = (const float*)d_in[i]; }
    const float* bias = (const float*)d_in[n_in - 1];

    float* out = (float*)d_out;

    // 524288 rows / 4 per quad / 8 quads per 256-thread block = 16384 blocks
    score_kernel<<<NROWS / 4 / 8, 256>>>(t1, t, w);
    softmax_kernel<<<Bc * Hc, 256>>>(padding, bias);
    scale_kernel<<<148 * 16, 256>>>(t, out);
    (void)out_size;
}

// round 4
// speedup vs baseline: 1.1760x; 1.0133x over previous
#include <cuda_runtime.h>
#include <math_constants.h>

// Problem shape (fixed by the dataset): B=32, H=16, N=1024, D=128, fp32.
#define Bc 32
#define Hc 16
#define Nc 1024
#define Dc 128
#define D4 (Dc / 4)                 // 32 float4 per row
#define NROWS (Bc * Hc * Nc)        // 524288 rows total

// Scratch (device globals; allocation is forbidden).
__device__ float g_score [NROWS];        // per-row score (t . w2)      2 MB
__device__ float g_part  [NROWS / 4];    // per-quad partial of t1 . w1 512 KB
__device__ float g_factor[NROWS];        // attn + 1                    2 MB

// ---------------------------------------------------------------------------
// Kernel A: one quad (4 consecutive rows, all within one bh) per warp.
// Lane split: g = lane>>3 (row in quad), sub = lane&7 (dim chunk).
// Lane reads float4 indices {sub, sub+8, sub+16, sub+24} of its row.
// ---------------------------------------------------------------------------
__global__ __launch_bounds__(256)
void score_kernel(const float* __restrict__ t1,
                  const float* __restrict__ t,
                  const float* __restrict__ w)      // [256]: w1 | w2
{
    const int warp  = (blockIdx.x * blockDim.x + threadIdx.x) >> 5;
    const int lane  = threadIdx.x & 31;
    const int g     = lane >> 3;
    const int sub   = lane & 7;

    const int quad = warp;                  // one quad per warp
    const int row  = quad * 4 + g;

    const float4* trow  = reinterpret_cast<const float4*>(t)  + (size_t)row * D4;
    const float4* t1row = reinterpret_cast<const float4*>(t1) + (size_t)row * D4;
    const float4* wf    = reinterpret_cast<const float4*>(w);

    // Issue all 16 data loads; weights are L1-broadcast hits.
    float4 c0 = __ldcs(trow  + sub);
    float4 c1 = __ldcs(trow  + sub + 8);
    float4 c2 = __ldcs(trow  + sub + 16);
    float4 c3 = __ldcs(trow  + sub + 24);
    float4 a0 = __ldcs(t1row + sub);
    float4 a1 = __ldcs(t1row + sub + 8);
    float4 a2 = __ldcs(t1row + sub + 16);
    float4 a3 = __ldcs(t1row + sub + 24);

    float4 u0 = wf[D4 + sub],      u1 = wf[D4 + sub + 8];
    float4 u2 = wf[D4 + sub + 16], u3 = wf[D4 + sub + 24];
    float4 v0 = wf[sub],           v1 = wf[sub + 8];
    float4 v2 = wf[sub + 16],      v3 = wf[sub + 24];

    float sc = c0.x*u0.x + c0.y*u0.y + c0.z*u0.z + c0.w*u0.w
             + c1.x*u1.x + c1.y*u1.y + c1.z*u1.z + c1.w*u1.w
             + c2.x*u2.x + c2.y*u2.y + c2.z*u2.z + c2.w*u2.w
             + c3.x*u3.x + c3.y*u3.y + c3.z*u3.z + c3.w*u3.w;

    float s1 = a0.x*v0.x + a0.y*v0.y + a0.z*v0.z + a0.w*v0.w
             + a1.x*v1.x + a1.y*v1.y + a1.z*v1.z + a1.w*v1.w
             + a2.x*v2.x + a2.y*v2.y + a2.z*v2.z + a2.w*v2.w
             + a3.x*v3.x + a3.y*v3.y + a3.z*v3.z + a3.w*v3.w;

    // 8-lane butterfly: reduces sc to per-row total, s1 partially.
    sc += __shfl_xor_sync(0xffffffffu, sc, 1);
    s1 += __shfl_xor_sync(0xffffffffu, s1, 1);
    sc += __shfl_xor_sync(0xffffffffu, sc, 2);
    s1 += __shfl_xor_sync(0xffffffffu, s1, 2);
    sc += __shfl_xor_sync(0xffffffffu, sc, 4);
    s1 += __shfl_xor_sync(0xffffffffu, s1, 4);
    // finish s1 across the 4 row-groups (full quad sum of t1 . w1)
    s1 += __shfl_xor_sync(0xffffffffu, s1, 8);
    s1 += __shfl_xor_sync(0xffffffffu, s1, 16);

    if (sub == 0) g_score[row] = sc;       // lanes 0,8,16,24
    if (lane == 0) g_part[quad] = s1;
}

// ---------------------------------------------------------------------------
// Kernel B: one block per (b,h). Reduce quad partials -> base, compute padd,
// softmax over scores, write factor = attn + 1.
// ---------------------------------------------------------------------------
__global__ __launch_bounds__(256)
void softmax_kernel(const int*   __restrict__ padding,
                    const float* __restrict__ bias)
{
    __shared__ float s_score[Nc];          // 4 KB
    __shared__ float s_red[8];
    __shared__ int   s_padd;

    const int bh   = blockIdx.x;
    const int b    = bh >> 4;              // Hc = 16
    const int tid  = threadIdx.x;
    const int wid  = tid >> 5;
    const int lane = tid & 31;

    if (tid == 0) s_padd = Nc;
    __syncthreads();

    // padd
    {
        const int* pb = padding + b * Nc;
        int local = Nc;
        #pragma unroll
        for (int n = tid; n < Nc; n += 256)
            if (pb[n] == 0) local = min(local, n);
        if (local < Nc) atomicMin(&s_padd, local);
    }

    // base = sum of 256 quad partials + bias
    float v = g_part[bh * (Nc / 4) + tid];
    #pragma unroll
    for (int o = 16; o > 0; o >>= 1) v += __shfl_xor_sync(0xffffffffu, v, o);
    if (lane == 0) s_red[wid] = v;
    __syncthreads();
    float base = bias[0];
    #pragma unroll
    for (int i = 0; i < 8; i++) base += s_red[i];
    const int padd = s_padd;

    // load scores + max over valid
    const float* sc_g = g_score + bh * Nc;
    float m = -CUDART_INF_F;
    #pragma unroll
    for (int n = tid; n < Nc; n += 256) {
        float sc = sc_g[n] + base;
        s_score[n] = sc;
        if (n < padd) m = fmaxf(m, sc);
    }
    #pragma unroll
    for (int o = 16; o > 0; o >>= 1)
        m = fmaxf(m, __shfl_xor_sync(0xffffffffu, m, o));
    __syncthreads();                        // reuse s_red
    if (lane == 0) s_red[wid] = m;
    __syncthreads();
    float mx = -CUDART_INF_F;
    #pragma unroll
    for (int i = 0; i < 8; i++) mx = fmaxf(mx, s_red[i]);

    float esum = 0.f;
    #pragma unroll
    for (int n = tid; n < Nc; n += 256) {
        float e = (n < padd) ? __expf(s_score[n] - mx) : 0.f;
        s_score[n] = e;
        esum += e;
    }
    #pragma unroll
    for (int o = 16; o > 0; o >>= 1)
        esum += __shfl_xor_sync(0xffffffffu, esum, o);
    __syncthreads();
    if (lane == 0) s_red[wid] = esum;
    __syncthreads();
    float tot = 0.f;
    #pragma unroll
    for (int i = 0; i < 8; i++) tot += s_red[i];
    const float inv = (tot > 0.f) ? (1.f / tot) : 0.f;

    float* fout = g_factor + bh * Nc;
    #pragma unroll
    for (int n = tid; n < Nc; n += 256)
        fout[n] = fmaf(s_score[n], inv, 1.f);
}

// ---------------------------------------------------------------------------
// Kernel C: out = t * factor[row].  Loop-free tile blocks, ILP = 4.
// One block owns a tile of 1024 float4 (= 32 rows). Thread t handles float4
// indices {t, t+256, t+512, t+768} -> each LDG/STG.128 instruction covers a
// contiguous 512B span (4 lines); factor index is warp-uniform per k.
// ---------------------------------------------------------------------------
__global__ __launch_bounds__(256)
void scale_kernel(const float* __restrict__ t, float* __restrict__ out)
{
    const size_t base = (size_t)blockIdx.x * 1024;
    const int    tid  = threadIdx.x;
    const float4* tv = reinterpret_cast<const float4*>(t);
    float4* ov = reinterpret_cast<float4*>(out);

    // Issue all 4 data loads back-to-back (independent, max MLP).
    float4 v0 = __ldcs(tv + base + tid);
    float4 v1 = __ldcs(tv + base + tid + 256);
    float4 v2 = __ldcs(tv + base + tid + 512);
    float4 v3 = __ldcs(tv + base + tid + 768);

    // Factor per k: row = base/32 + k*8 + (tid>>5); warp-uniform broadcast.
    const int row0 = (int)(base >> 5) + (tid >> 5);
    float f0 = g_factor[row0];
    float f1 = g_factor[row0 + 8];
    float f2 = g_factor[row0 + 16];
    float f3 = g_factor[row0 + 24];

    v0.x *= f0; v0.y *= f0; v0.z *= f0; v0.w *= f0;
    v1.x *= f1; v1.y *= f1; v1.z *= f1; v1.w *= f1;
    v2.x *= f2; v2.y *= f2; v2.z *= f2; v2.w *= f2;
    v3.x *= f3; v3.y *= f3; v3.z *= f3; v3.w *= f3;

    __stcs(ov + base + tid,       v0);
    __stcs(ov + base + tid + 256, v1);
    __stcs(ov + base + tid + 512, v2);
    __stcs(ov + base + tid + 768, v3);
}

extern "C" void kernel_launch(void* const* d_in, const int* in_sizes, int n_in,
                              void* d_out, int out_size)
{
    const float* t1      = (const float*)d_in[0];
    const float* t       = (const float*)d_in[1];
    const int*   padding = (const int*)d_in[2];

    const float* w = nullptr;
    for (int i = 3; i < n_in; i++)
        if (in_sizes[i] == 2 * Dc) { w = (const float*)d_in[i]; }
    const float* bias = (const float*)d_in[n_in - 1];

    float* out = (float*)d_out;

    // 524288 rows / 4 per quad / 8 quads per 256-thread block = 16384 blocks
    score_kernel<<<NROWS / 4 / 8, 256>>>(t1, t, w);
    softmax_kernel<<<Bc * Hc, 256>>>(padding, bias);
    // 16,777,216 float4 / 1024 per tile = 16384 blocks
    scale_kernel<<<16384, 256>>>(t, out);
    (void)out_size;
}